// round 2
// baseline (speedup 1.0000x reference)
#include <cuda_runtime.h>
#include <math.h>

#define D_MODEL 512
#define D_LOW   64
#define NUM_BINS 39
#define DIST_MIN_F 2.0f
#define DIST_MAX_F 22.0f
#define BIN_W  ((DIST_MAX_F - DIST_MIN_F) / (float)(NUM_BINS - 1))
#define LN_EPS 1e-5f

#define MAX_ROWS 4096

__device__ float g_U[MAX_ROWS * D_LOW];
__device__ float g_V[MAX_ROWS * D_LOW];
__device__ double g_ce[8];
__device__ unsigned int g_cnt[8];

// ---------------------------------------------------------------------------
// Kernel 1: LayerNorm + U/V projections. One 128-thread block per token row.
// ---------------------------------------------------------------------------
__global__ void __launch_bounds__(128) prep_kernel(
    const float* __restrict__ h_res,
    const float* __restrict__ ln_w, const float* __restrict__ ln_b,
    const float* __restrict__ wu_w, const float* __restrict__ wu_b,
    const float* __restrict__ wv_w, const float* __restrict__ wv_b)
{
    __shared__ __align__(16) float sh[D_MODEL];
    __shared__ float rs[4], rq[4];
    __shared__ float s_mu, s_istd;

    int r = blockIdx.x;
    int t = threadIdx.x;

    // zero the global accumulators once per launch (block 0 only; main kernel
    // runs after this kernel completes, stream-ordered)
    if (r == 0 && t < 8) { g_ce[t] = 0.0; g_cnt[t] = 0u; }

    float4 hv = reinterpret_cast<const float4*>(h_res)[(size_t)r * (D_MODEL/4) + t];
    float s  = hv.x + hv.y + hv.z + hv.w;
    float sq = hv.x*hv.x + hv.y*hv.y + hv.z*hv.z + hv.w*hv.w;
    #pragma unroll
    for (int o = 16; o > 0; o >>= 1) {
        s  += __shfl_down_sync(0xffffffffu, s,  o);
        sq += __shfl_down_sync(0xffffffffu, sq, o);
    }
    if ((t & 31) == 0) { rs[t >> 5] = s; rq[t >> 5] = sq; }
    __syncthreads();
    if (t == 0) {
        float S = rs[0] + rs[1] + rs[2] + rs[3];
        float Q = rq[0] + rq[1] + rq[2] + rq[3];
        float mu  = S * (1.0f / (float)D_MODEL);
        float var = Q * (1.0f / (float)D_MODEL) - mu * mu;
        s_mu = mu;
        s_istd = rsqrtf(var + LN_EPS);
    }
    __syncthreads();
    float mu = s_mu, istd = s_istd;

    float4 w4 = reinterpret_cast<const float4*>(ln_w)[t];
    float4 b4 = reinterpret_cast<const float4*>(ln_b)[t];
    float4 nv;
    nv.x = (hv.x - mu) * istd * w4.x + b4.x;
    nv.y = (hv.y - mu) * istd * w4.y + b4.y;
    nv.z = (hv.z - mu) * istd * w4.z + b4.z;
    nv.w = (hv.w - mu) * istd * w4.w + b4.w;
    reinterpret_cast<float4*>(sh)[t] = nv;
    __syncthreads();

    // thread t < 64 computes U[r][t]; t >= 64 computes V[r][t-64]
    const float* wrow = (t < D_LOW) ? (wu_w + (size_t)t * D_MODEL)
                                    : (wv_w + (size_t)(t - D_LOW) * D_MODEL);
    const float4* w4p = reinterpret_cast<const float4*>(wrow);
    const float4* h4p = reinterpret_cast<const float4*>(sh);
    float acc = 0.0f;
    #pragma unroll 8
    for (int c = 0; c < D_MODEL/4; c++) {
        float4 a = w4p[c];
        float4 x = h4p[c];
        acc = fmaf(a.x, x.x, fmaf(a.y, x.y, fmaf(a.z, x.z, fmaf(a.w, x.w, acc))));
    }
    if (t < D_LOW) g_U[(size_t)r * D_LOW + t]            = acc + wu_b[t];
    else           g_V[(size_t)r * D_LOW + (t - D_LOW)]  = acc + wv_b[t - D_LOW];
}

// ---------------------------------------------------------------------------
// Kernel 2: fused logits + softmax-CE over 16x16 pair tiles, one pair/thread.
// ---------------------------------------------------------------------------
#define TI 16
#define TJ 16

__global__ void __launch_bounds__(256) main_kernel(
    const float* __restrict__ x_true, const float* __restrict__ pad,
    const float* __restrict__ wb_w,  const float* __restrict__ wb_b,
    int B, int N)
{
    // U/V tiles padded to stride 68 floats (272B) -> conflict-free LDS.128
    __shared__ __align__(16) float Us[TI * 68];
    __shared__ __align__(16) float Vs[TJ * 68];
    __shared__ __align__(16) float Wbs[NUM_BINS * D_LOW];
    __shared__ float wbb[40];
    __shared__ float sxi[TI][4];  // x,y,z,pad
    __shared__ float sxj[TJ][4];
    __shared__ float wce[8];
    __shared__ unsigned wcc[8];

    int b  = blockIdx.z;
    int i0 = blockIdx.y * TI;
    int j0 = blockIdx.x * TJ;
    int tid = threadIdx.x;

    for (int idx = tid; idx < TI * D_LOW; idx += 256) {
        int rr = idx >> 6, c = idx & 63;
        int gi = i0 + rr, gj = j0 + rr;
        Us[rr * 68 + c] = (gi < N) ? g_U[((size_t)b * N + gi) * D_LOW + c] : 0.0f;
        Vs[rr * 68 + c] = (gj < N) ? g_V[((size_t)b * N + gj) * D_LOW + c] : 0.0f;
    }
    for (int idx = tid; idx < NUM_BINS * D_LOW; idx += 256) Wbs[idx] = wb_w[idx];
    if (tid < NUM_BINS) wbb[tid] = wb_b[tid];
    if (tid < TI) {
        int gi = i0 + tid;
        if (gi < N) {
            size_t base = ((size_t)b * N + gi) * 3;
            sxi[tid][0] = x_true[base + 0];
            sxi[tid][1] = x_true[base + 1];
            sxi[tid][2] = x_true[base + 2];
            sxi[tid][3] = pad[(size_t)b * N + gi];
        } else {
            sxi[tid][0] = sxi[tid][1] = sxi[tid][2] = 0.0f;
            sxi[tid][3] = 0.0f;
        }
    } else if (tid < 2 * TI) {
        int r = tid - TI;
        int gj = j0 + r;
        if (gj < N) {
            size_t base = ((size_t)b * N + gj) * 3;
            sxj[r][0] = x_true[base + 0];
            sxj[r][1] = x_true[base + 1];
            sxj[r][2] = x_true[base + 2];
            sxj[r][3] = pad[(size_t)b * N + gj];
        } else {
            sxj[r][0] = sxj[r][1] = sxj[r][2] = 0.0f;
            sxj[r][3] = 0.0f;
        }
    }
    __syncthreads();

    int ti = tid >> 4;
    int tj = tid & 15;

    float acc[NUM_BINS];
    #pragma unroll
    for (int k = 0; k < NUM_BINS; k++) acc[k] = wbb[k];

    const float4* u4p = reinterpret_cast<const float4*>(Us + ti * 68);
    const float4* v4p = reinterpret_cast<const float4*>(Vs + tj * 68);
    const float4* wb4 = reinterpret_cast<const float4*>(Wbs);

    #pragma unroll 1
    for (int c4 = 0; c4 < D_LOW/4; c4++) {
        float4 u = u4p[c4];
        float4 v = v4p[c4];
        float4 w;
        w.x = u.x * v.x; w.y = u.y * v.y; w.z = u.z * v.z; w.w = u.w * v.w;
        #pragma unroll
        for (int k = 0; k < NUM_BINS; k++) {
            float4 q = wb4[k * (D_LOW/4) + c4];
            acc[k] = fmaf(w.x, q.x, fmaf(w.y, q.y, fmaf(w.z, q.z, fmaf(w.w, q.w, acc[k]))));
        }
    }

    // target bin from pairwise distance (trunc-to-int, clamp — matches ref)
    float dx = sxi[ti][0] - sxj[tj][0];
    float dy = sxi[ti][1] - sxj[tj][1];
    float dz = sxi[ti][2] - sxj[tj][2];
    float d  = sqrtf(dx*dx + dy*dy + dz*dz);
    int bin  = (int)((d - DIST_MIN_F) / BIN_W);
    bin = min(max(bin, 0), NUM_BINS - 1);

    // softmax cross-entropy: ce = logsumexp(acc) - acc[bin]
    float m = -1e30f;
    #pragma unroll
    for (int k = 0; k < NUM_BINS; k++) m = fmaxf(m, acc[k]);
    float ssum = 0.0f, tl = 0.0f;
    #pragma unroll
    for (int k = 0; k < NUM_BINS; k++) {
        ssum += __expf(acc[k] - m);
        if (k == bin) tl = acc[k];   // predicated select, no dynamic indexing
    }
    float ce = (m + __logf(ssum)) - tl;

    bool ok = ((i0 + ti) < N) && ((j0 + tj) < N) && (sxi[ti][3] * sxj[tj][3] > 0.0f);
    float cv = ok ? ce : 0.0f;
    unsigned cc = ok ? 1u : 0u;

    #pragma unroll
    for (int o = 16; o > 0; o >>= 1) {
        cv += __shfl_down_sync(0xffffffffu, cv, o);
        cc += __shfl_down_sync(0xffffffffu, cc, o);
    }
    int lane = tid & 31, wrp = tid >> 5;
    if (lane == 0) { wce[wrp] = cv; wcc[wrp] = cc; }
    __syncthreads();
    if (tid == 0) {
        float S = 0.0f; unsigned C = 0u;
        #pragma unroll
        for (int q = 0; q < 8; q++) { S += wce[q]; C += wcc[q]; }
        atomicAdd(&g_ce[b], (double)S);
        atomicAdd(&g_cnt[b], C);
    }
}

// ---------------------------------------------------------------------------
// Kernel 3: final scalar
// ---------------------------------------------------------------------------
__global__ void finalize_kernel(float* out, int B)
{
    double loss = 0.0;
    int valid = 0;
    for (int b = 0; b < B; b++) {
        if (g_cnt[b] > 0u) { loss += g_ce[b] / (double)g_cnt[b]; valid++; }
    }
    out[0] = (float)(valid > 0 ? loss / (double)valid : 0.0);
}

// ---------------------------------------------------------------------------
extern "C" void kernel_launch(void* const* d_in, const int* in_sizes, int n_in,
                              void* d_out, int out_size)
{
    const float* h_res  = (const float*)d_in[0];
    const float* x_true = (const float*)d_in[1];
    const float* padm   = (const float*)d_in[2];
    const float* ln_w   = (const float*)d_in[3];
    const float* ln_b   = (const float*)d_in[4];
    const float* wu_w   = (const float*)d_in[5];
    const float* wu_b   = (const float*)d_in[6];
    const float* wv_w   = (const float*)d_in[7];
    const float* wv_b   = (const float*)d_in[8];
    const float* wb_w   = (const float*)d_in[9];
    const float* wb_b   = (const float*)d_in[10];

    int BN = in_sizes[0] / D_MODEL;   // B*N
    int B = 2;
    int N = BN / B;

    prep_kernel<<<BN, 128>>>(h_res, ln_w, ln_b, wu_w, wu_b, wv_w, wv_b);

    dim3 grid((N + TJ - 1) / TJ, (N + TI - 1) / TI, B);
    main_kernel<<<grid, 256>>>(x_true, padm, wb_w, wb_b, B, N);

    finalize_kernel<<<1, 1>>>((float*)d_out, B);
}